// round 1
// baseline (speedup 1.0000x reference)
#include <cuda_runtime.h>
#include <math.h>

#define N_TASKS 8192
#define DDIM 64
#define EDIM 64
#define BB 2
#define TJ 64
#define TI 64
#define STR 68           // smem row stride in floats (68*4B=272B, 16B-aligned rows)
#define LEAK 0.7f

// Scratch for V = U @ W  [N, E]  (device global: no runtime allocation)
__device__ float g_V[N_TASKS * EDIM];

// ---------------------------------------------------------------------------
// Kernel 1: V[i,f] = sum_e U[i,e] * W[e,f]   (tiny: 67 MFLOP)
// ---------------------------------------------------------------------------
__global__ void __launch_bounds__(256) compute_V_kernel(
    const float* __restrict__ U, const float* __restrict__ W)
{
    __shared__ float sW[EDIM][EDIM + 1];
    __shared__ float sU[64][EDIM + 1];
    const int t = threadIdx.x;
    const int blk = blockIdx.x;            // 128 blocks x 64 rows

    for (int idx = t; idx < EDIM * EDIM; idx += 256)
        sW[idx / EDIM][idx % EDIM] = W[idx];
    for (int idx = t; idx < 64 * EDIM; idx += 256) {
        int r = idx / EDIM, e = idx % EDIM;
        sU[r][e] = U[(blk * 64 + r) * EDIM + e];
    }
    __syncthreads();

    const int i  = t / 4;                  // 0..63
    const int f0 = (t % 4) * 16;           // 16 cols per thread
    float acc[16];
#pragma unroll
    for (int k = 0; k < 16; k++) acc[k] = 0.f;
    for (int e = 0; e < EDIM; e++) {
        float u = sU[i][e];
#pragma unroll
        for (int k = 0; k < 16; k++) acc[k] = fmaf(u, sW[e][f0 + k], acc[k]);
    }
#pragma unroll
    for (int k = 0; k < 16; k++)
        g_V[(blk * 64 + i) * EDIM + f0 + k] = acc[k];
}

// ---------------------------------------------------------------------------
// Kernel 2: fused  T = sigmoid(V Uj^T + b)  (diag-masked)  and
//           out[b,j,:] = states[b,j,:] + sum_i g_b[i] * T[i,j] * states[b,i,:]
// Grid: 128 CTAs (one per 64-wide j-tile), 256 threads.
// ---------------------------------------------------------------------------
__global__ void __launch_bounds__(256) fused_transfer_kernel(
    const float* __restrict__ states,   // [B, N, D]
    const float* __restrict__ prof,     // [B, N]
    const float* __restrict__ U,        // [N, E]
    const float* __restrict__ bias_ptr, // [1]
    float* __restrict__ out)            // [B, N, D]
{
    extern __shared__ float smem[];
    float* sU = smem;                       // [TJ][STR]  U rows of j-tile
    float* sV = sU + TJ * STR;              // [TI][STR]  V rows of i-tile
    float* sE = sV + TI * STR;              // [BB][TI][STR] gated states
    float* sP = sE + BB * TI * STR;         // [TI][STR]  P tile (i x j)

    const int t  = threadIdx.x;
    const int jt = blockIdx.x;
    const int tx = t % 16;                  // 16
    const int ty = t / 16;                  // 16
    const float bias = bias_ptr[0];

    // Load U_j tile once (rows j, cols e)
    for (int idx = t; idx < TJ * EDIM; idx += 256) {
        int r = idx / EDIM, e = idx % EDIM;
        sU[r * STR + e] = U[(jt * TJ + r) * EDIM + e];
    }

    float acc[BB][4][4];
#pragma unroll
    for (int b = 0; b < BB; b++)
#pragma unroll
        for (int r = 0; r < 4; r++)
#pragma unroll
            for (int c = 0; c < 4; c++) acc[b][r][c] = 0.f;

    for (int it = 0; it < N_TASKS / TI; it++) {
        __syncthreads();   // previous phase-B done before overwriting sV/sE

        // Load V_i tile
        for (int idx = t; idx < TI * EDIM; idx += 256) {
            int r = idx / EDIM, e = idx % EDIM;
            sV[r * STR + e] = g_V[(it * TI + r) * EDIM + e];
        }
        // Load gated states tiles (both batches), float4 granularity
        for (int idx = t; idx < BB * TI * (DDIM / 4); idx += 256) {
            int d4 = idx % 16;
            int r  = (idx / 16) % TI;
            int b  = idx / (16 * TI);
            int ig = it * TI + r;
            float g = prof[b * N_TASKS + ig] - LEAK;
            g = g > 0.f ? g : 0.f;
            float4 s4 = *(const float4*)&states[((size_t)b * N_TASKS + ig) * DDIM + d4 * 4];
            float4 e4;
            e4.x = s4.x * g; e4.y = s4.y * g; e4.z = s4.z * g; e4.w = s4.w * g;
            *(float4*)&sE[(b * TI + r) * STR + d4 * 4] = e4;
        }
        __syncthreads();

        // ---- Phase A: S[i,j] = sum_e V[i,e] * U[j,e], 4x4 per thread ----
        float s[4][4];
#pragma unroll
        for (int r = 0; r < 4; r++)
#pragma unroll
            for (int c = 0; c < 4; c++) s[r][c] = 0.f;

        for (int e0 = 0; e0 < EDIM; e0 += 4) {
            float4 av[4], bu[4];
#pragma unroll
            for (int r = 0; r < 4; r++)
                av[r] = *(const float4*)&sV[(ty * 4 + r) * STR + e0];
#pragma unroll
            for (int c = 0; c < 4; c++)
                bu[c] = *(const float4*)&sU[(tx * 4 + c) * STR + e0];
#pragma unroll
            for (int r = 0; r < 4; r++)
#pragma unroll
                for (int c = 0; c < 4; c++) {
                    s[r][c] = fmaf(av[r].x, bu[c].x, s[r][c]);
                    s[r][c] = fmaf(av[r].y, bu[c].y, s[r][c]);
                    s[r][c] = fmaf(av[r].z, bu[c].z, s[r][c]);
                    s[r][c] = fmaf(av[r].w, bu[c].w, s[r][c]);
                }
        }

        // sigmoid + bias + diagonal mask, write P tile
#pragma unroll
        for (int r = 0; r < 4; r++) {
            int il = ty * 4 + r;
            int ig = it * TI + il;
            float4 p4;
            float* pv = &p4.x;
#pragma unroll
            for (int c = 0; c < 4; c++) {
                int jg = jt * TJ + tx * 4 + c;
                float p = 1.0f / (1.0f + expf(-(s[r][c] + bias)));
                if (ig == jg) p = 0.f;
                pv[c] = p;
            }
            *(float4*)&sP[il * STR + tx * 4] = p4;
        }
        __syncthreads();

        // ---- Phase B: acc[b][j][d] += P[i,j] * Eff[b,i,d] ----
#pragma unroll 4
        for (int i = 0; i < TI; i++) {
            float4 p4 = *(const float4*)&sP[i * STR + ty * 4];
            float4 e0 = *(const float4*)&sE[(0 * TI + i) * STR + tx * 4];
            float4 e1 = *(const float4*)&sE[(1 * TI + i) * STR + tx * 4];
            const float pj[4] = {p4.x, p4.y, p4.z, p4.w};
            const float ed0[4] = {e0.x, e0.y, e0.z, e0.w};
            const float ed1[4] = {e1.x, e1.y, e1.z, e1.w};
#pragma unroll
            for (int r = 0; r < 4; r++)
#pragma unroll
                for (int c = 0; c < 4; c++) {
                    acc[0][r][c] = fmaf(pj[r], ed0[c], acc[0][r][c]);
                    acc[1][r][c] = fmaf(pj[r], ed1[c], acc[1][r][c]);
                }
        }
    }

    // Epilogue: out = states + acc
#pragma unroll
    for (int b = 0; b < BB; b++)
#pragma unroll
        for (int r = 0; r < 4; r++) {
            int jg = jt * TJ + ty * 4 + r;
            size_t off = ((size_t)b * N_TASKS + jg) * DDIM + tx * 4;
            float4 s4 = *(const float4*)&states[off];
            float4 o;
            o.x = s4.x + acc[b][r][0];
            o.y = s4.y + acc[b][r][1];
            o.z = s4.z + acc[b][r][2];
            o.w = s4.w + acc[b][r][3];
            *(float4*)&out[off] = o;
        }
}

// ---------------------------------------------------------------------------
extern "C" void kernel_launch(void* const* d_in, const int* in_sizes, int n_in,
                              void* d_out, int out_size)
{
    const float* states = (const float*)d_in[0];   // [2, 8192, 64]
    const float* prof   = (const float*)d_in[1];   // [2, 8192]
    const float* U      = (const float*)d_in[2];   // [8192, 64]
    const float* W      = (const float*)d_in[3];   // [1, 64, 64]
    const float* bias   = (const float*)d_in[4];   // [1]
    float* out          = (float*)d_out;           // [2, 8192, 64]

    const int smem_bytes = (TJ + TI + BB * TI + TI) * STR * sizeof(float); // ~87 KB
    // Idempotent; legal during capture (host-side attribute, no stream work)
    cudaFuncSetAttribute(fused_transfer_kernel,
                         cudaFuncAttributeMaxDynamicSharedMemorySize, smem_bytes);

    compute_V_kernel<<<N_TASKS / 64, 256>>>(U, W);
    fused_transfer_kernel<<<N_TASKS / TJ, 256, smem_bytes>>>(states, prof, U, bias, out);
}

// round 2
// speedup vs baseline: 1.4217x; 1.4217x over previous
#include <cuda_runtime.h>
#include <math.h>

#define N_TASKS 8192
#define DDIM 64
#define EDIM 64
#define BB 2
#define TJ 64
#define TI 64
#define STR 68            // smem row stride in floats; rows stay 16B-aligned
#define LEAK 0.7f

// Transposed scratch (device globals: no runtime allocation)
__device__ float g_Vt[EDIM * N_TASKS];   // [e][i] : V = U @ W, transposed
__device__ float g_Ut[EDIM * N_TASKS];   // [e][j] : U transposed

// ---------------- packed f32x2 helpers (FFMA2 path) ------------------------
__device__ __forceinline__ unsigned long long ffma2(
    unsigned long long a, unsigned long long b, unsigned long long c)
{
    unsigned long long d;
    asm("fma.rn.f32x2 %0, %1, %2, %3;" : "=l"(d) : "l"(a), "l"(b), "l"(c));
    return d;
}
__device__ __forceinline__ unsigned long long fadd2(
    unsigned long long a, unsigned long long b)
{
    unsigned long long d;
    asm("add.rn.f32x2 %0, %1, %2;" : "=l"(d) : "l"(a), "l"(b));
    return d;
}
__device__ __forceinline__ unsigned long long dup2(float x)
{
    unsigned long long r;
    asm("mov.b64 %0, {%1, %1};" : "=l"(r) : "f"(x));
    return r;
}
__device__ __forceinline__ float2 unpk(unsigned long long v)
{
    float2 f;
    asm("mov.b64 {%0, %1}, %2;" : "=f"(f.x), "=f"(f.y) : "l"(v));
    return f;
}

// ---------------------------------------------------------------------------
// Kernel 1: V = U @ W, written transposed; also transpose U. (~67 MFLOP, tiny)
// ---------------------------------------------------------------------------
__global__ void __launch_bounds__(256) prep_kernel(
    const float* __restrict__ U, const float* __restrict__ W)
{
    __shared__ float sW[EDIM][EDIM + 1];
    __shared__ float sU[64][EDIM + 1];
    const int t = threadIdx.x;
    const int blk = blockIdx.x;             // 128 blocks x 64 rows

    for (int idx = t; idx < EDIM * EDIM; idx += 256)
        sW[idx / EDIM][idx % EDIM] = W[idx];
    for (int idx = t; idx < 64 * EDIM; idx += 256) {
        int r = idx / EDIM, e = idx % EDIM;
        sU[r][e] = U[(blk * 64 + r) * EDIM + e];
    }
    __syncthreads();

    const int i  = t / 4;
    const int f0 = (t % 4) * 16;
    float acc[16];
#pragma unroll
    for (int k = 0; k < 16; k++) acc[k] = 0.f;
    for (int e = 0; e < EDIM; e++) {
        float u = sU[i][e];
#pragma unroll
        for (int k = 0; k < 16; k++) acc[k] = fmaf(u, sW[e][f0 + k], acc[k]);
    }
#pragma unroll
    for (int k = 0; k < 16; k++)
        g_Vt[(f0 + k) * N_TASKS + blk * 64 + i] = acc[k];

    // U transposed copy (coalesced along i; conflict-free LDS)
    for (int idx = t; idx < EDIM * 64; idx += 256) {
        int e = idx / 64, i2 = idx % 64;
        g_Ut[e * N_TASKS + blk * 64 + i2] = sU[i2][e];
    }
}

// ---------------------------------------------------------------------------
// Kernel 2: fused transfer. 512 threads, FFMA2 microkernels.
// ---------------------------------------------------------------------------
__global__ void __launch_bounds__(512) fused_transfer_kernel(
    const float* __restrict__ states,   // [B, N, D]
    const float* __restrict__ prof,     // [B, N]
    const float* __restrict__ bias_ptr, // [1]
    float* __restrict__ out)            // [B, N, D]
{
    extern __shared__ float smem[];
    float* sUt = smem;                      // [E=64][STR]  U^T, cols = j-tile
    float* sVt = sUt + EDIM * STR;          // [E=64][STR]  V^T, cols = i-tile
    float* sE  = sVt + EDIM * STR;          // [B][TI][STR] gated states (d contig)
    float* sP  = sE + BB * TI * STR;        // [TI][STR]    P tile (j contig)

    const int t  = threadIdx.x;
    const int jt = blockIdx.x;
    const float bias = bias_ptr[0];

    // phase-A mapping: 16 x 32 thread grid; 2 i-rows x 4 j-cols microtile
    const int tx = t % 16;
    const int ty = t / 16;
    // phase-B mapping: two halves over i; within half: 16 d-grp x 16 j-grp
    const int half = t >> 8;
    const int tb = t & 255;
    const int bx = tb % 16;                 // 4 d-cols
    const int by = tb / 16;                 // 4 j-rows

    // Load U^T tile once (rows e, cols j)
    for (int idx = t; idx < EDIM * 16; idx += 512) {
        int e = idx / 16, j4 = idx % 16;
        *(float4*)&sUt[e * STR + j4 * 4] =
            *(const float4*)&g_Ut[e * N_TASKS + jt * TJ + j4 * 4];
    }

    unsigned long long acc2[BB][4][2];      // [b][j-row][d-pair]
#pragma unroll
    for (int b = 0; b < BB; b++)
#pragma unroll
        for (int r = 0; r < 4; r++) { acc2[b][r][0] = 0ull; acc2[b][r][1] = 0ull; }

    for (int it = 0; it < N_TASKS / TI; it++) {
        __syncthreads();    // prior phase-B done before overwriting sVt/sE/sP

        // fill V^T tile (rows e, cols i) — straight float4 copies
        for (int idx = t; idx < EDIM * 16; idx += 512) {
            int e = idx / 16, i4 = idx % 16;
            *(float4*)&sVt[e * STR + i4 * 4] =
                *(const float4*)&g_Vt[e * N_TASKS + it * TI + i4 * 4];
        }
        // fill gated states (both batches)
        for (int idx = t; idx < BB * TI * 16; idx += 512) {
            int d4 = idx % 16;
            int r  = (idx / 16) % TI;
            int b  = idx / (16 * TI);
            int ig = it * TI + r;
            float g = prof[b * N_TASKS + ig] - LEAK;
            g = g > 0.f ? g : 0.f;
            float4 s4 = *(const float4*)&states[((size_t)b * N_TASKS + ig) * DDIM + d4 * 4];
            float4 e4;
            e4.x = s4.x * g; e4.y = s4.y * g; e4.z = s4.z * g; e4.w = s4.w * g;
            *(float4*)&sE[(b * TI + r) * STR + d4 * 4] = e4;
        }
        __syncthreads();

        // ---- Phase A: S[i,j] = sum_e V[i,e]*U[j,e]; 2x4 per thread, FFMA2 ----
        unsigned long long s2a[2][2] = {{0ull, 0ull}, {0ull, 0ull}};
#pragma unroll 8
        for (int e = 0; e < EDIM; e++) {
            float2 av = *(const float2*)&sVt[e * STR + ty * 2];
            ulonglong2 bu = *(const ulonglong2*)&sUt[e * STR + tx * 4];
            unsigned long long a0 = dup2(av.x), a1 = dup2(av.y);
            s2a[0][0] = ffma2(a0, bu.x, s2a[0][0]);
            s2a[0][1] = ffma2(a0, bu.y, s2a[0][1]);
            s2a[1][0] = ffma2(a1, bu.x, s2a[1][0]);
            s2a[1][1] = ffma2(a1, bu.y, s2a[1][1]);
        }

        // sigmoid + bias + diag mask, write P tile
#pragma unroll
        for (int r = 0; r < 2; r++) {
            int il = ty * 2 + r;
            int ig = it * TI + il;
            float2 p0 = unpk(s2a[r][0]);
            float2 p1 = unpk(s2a[r][1]);
            float v[4] = {p0.x, p0.y, p1.x, p1.y};
            float4 pw;
            float* pv = &pw.x;
#pragma unroll
            for (int c = 0; c < 4; c++) {
                int jg = jt * TJ + tx * 4 + c;
                float x = v[c] + bias;
                float p = 1.0f / (1.0f + __expf(-x));
                if (ig == jg) p = 0.f;
                pv[c] = p;
            }
            *(float4*)&sP[il * STR + tx * 4] = pw;
        }
        __syncthreads();

        // ---- Phase B: acc[b][j][d] += P[i,j]*Eff[b,i,d]; half-split i ----
        const int ibase = half * 32;
#pragma unroll 4
        for (int ii = 0; ii < 32; ii++) {
            int i = ibase + ii;
            float4 pj = *(const float4*)&sP[i * STR + by * 4];
            ulonglong2 e0 = *(const ulonglong2*)&sE[(0 * TI + i) * STR + bx * 4];
            ulonglong2 e1 = *(const ulonglong2*)&sE[(1 * TI + i) * STR + bx * 4];
            unsigned long long p0 = dup2(pj.x), p1 = dup2(pj.y),
                               p2 = dup2(pj.z), p3 = dup2(pj.w);
            acc2[0][0][0] = ffma2(p0, e0.x, acc2[0][0][0]);
            acc2[0][0][1] = ffma2(p0, e0.y, acc2[0][0][1]);
            acc2[0][1][0] = ffma2(p1, e0.x, acc2[0][1][0]);
            acc2[0][1][1] = ffma2(p1, e0.y, acc2[0][1][1]);
            acc2[0][2][0] = ffma2(p2, e0.x, acc2[0][2][0]);
            acc2[0][2][1] = ffma2(p2, e0.y, acc2[0][2][1]);
            acc2[0][3][0] = ffma2(p3, e0.x, acc2[0][3][0]);
            acc2[0][3][1] = ffma2(p3, e0.y, acc2[0][3][1]);
            acc2[1][0][0] = ffma2(p0, e1.x, acc2[1][0][0]);
            acc2[1][0][1] = ffma2(p0, e1.y, acc2[1][0][1]);
            acc2[1][1][0] = ffma2(p1, e1.x, acc2[1][1][0]);
            acc2[1][1][1] = ffma2(p1, e1.y, acc2[1][1][1]);
            acc2[1][2][0] = ffma2(p2, e1.x, acc2[1][2][0]);
            acc2[1][2][1] = ffma2(p2, e1.y, acc2[1][2][1]);
            acc2[1][3][0] = ffma2(p3, e1.x, acc2[1][3][0]);
            acc2[1][3][1] = ffma2(p3, e1.y, acc2[1][3][1]);
        }
    }

    // ---- Epilogue: combine halves, add states, write out ----
    __syncthreads();
    if (half == 1) {
        // stash partial accumulators in sE scratch (8192 floats needed, fits)
        unsigned long long* dst = (unsigned long long*)&sE[tb * 32];
#pragma unroll
        for (int b = 0; b < BB; b++)
#pragma unroll
            for (int r = 0; r < 4; r++) {
                dst[(b * 4 + r) * 2 + 0] = acc2[b][r][0];
                dst[(b * 4 + r) * 2 + 1] = acc2[b][r][1];
            }
    }
    __syncthreads();
    if (half == 0) {
        const unsigned long long* src = (const unsigned long long*)&sE[tb * 32];
#pragma unroll
        for (int b = 0; b < BB; b++)
#pragma unroll
            for (int r = 0; r < 4; r++) {
                unsigned long long t0 = fadd2(acc2[b][r][0], src[(b * 4 + r) * 2 + 0]);
                unsigned long long t1 = fadd2(acc2[b][r][1], src[(b * 4 + r) * 2 + 1]);
                float2 f0 = unpk(t0), f1 = unpk(t1);
                int jg = jt * TJ + by * 4 + r;
                size_t off = ((size_t)b * N_TASKS + jg) * DDIM + bx * 4;
                float4 s4 = *(const float4*)&states[off];
                float4 o;
                o.x = s4.x + f0.x; o.y = s4.y + f0.y;
                o.z = s4.z + f1.x; o.w = s4.w + f1.y;
                *(float4*)&out[off] = o;
            }
    }
}

// ---------------------------------------------------------------------------
extern "C" void kernel_launch(void* const* d_in, const int* in_sizes, int n_in,
                              void* d_out, int out_size)
{
    const float* states = (const float*)d_in[0];   // [2, 8192, 64]
    const float* prof   = (const float*)d_in[1];   // [2, 8192]
    const float* U      = (const float*)d_in[2];   // [8192, 64]
    const float* W      = (const float*)d_in[3];   // [1, 64, 64]
    const float* bias   = (const float*)d_in[4];   // [1]
    float* out          = (float*)d_out;           // [2, 8192, 64]

    const int smem_bytes = (EDIM + EDIM + BB * TI + TI) * STR * sizeof(float); // 87040
    cudaFuncSetAttribute(fused_transfer_kernel,
                         cudaFuncAttributeMaxDynamicSharedMemorySize, smem_bytes);

    prep_kernel<<<N_TASKS / 64, 256>>>(U, W);
    fused_transfer_kernel<<<N_TASKS / TJ, 512, smem_bytes>>>(states, prof, bias, out);
}

// round 10
// speedup vs baseline: 12.0491x; 8.4752x over previous
#include <cuda_runtime.h>
#include <cuda_fp16.h>
#include <cstdint>
#include <math.h>

#define N_TASKS 8192
#define EDIM 64
#define DDIM 64
#define BB 2
#define NT 32           // i-tiles per CTA (half of N / 128)
#define LEAK 0.7f

// ---------------- device scratch (no runtime allocation) -------------------
__device__ __half g_Uh[N_TASKS * EDIM];            // fp16 U  [i][e]
__device__ __half g_Vh[N_TASKS * EDIM];            // fp16 V=U@W  [i][e]
__device__ __half g_Et[BB * DDIM * N_TASKS];       // fp16 gated states^T [b][d][i]
__device__ float  g_part[2 * BB * N_TASKS * DDIM]; // partial leaked [half][b][j][d]

// ---------------- PTX helpers ----------------------------------------------
__device__ __forceinline__ uint32_t smem_u32(const void* p) {
    uint32_t a;
    asm("{ .reg .u64 t; cvta.to.shared.u64 t, %1; cvt.u32.u64 %0, t; }" : "=r"(a) : "l"(p));
    return a;
}
__device__ __forceinline__ void cp16(uint32_t dst, const void* src) {
    asm volatile("cp.async.ca.shared.global [%0], [%1], 16;" :: "r"(dst), "l"(src) : "memory");
}
__device__ __forceinline__ void cp_commit() {
    asm volatile("cp.async.commit_group;" ::: "memory");
}
__device__ __forceinline__ void ldsm4(uint32_t& r0, uint32_t& r1, uint32_t& r2, uint32_t& r3,
                                      uint32_t addr) {
    asm volatile("ldmatrix.sync.aligned.m8n8.x4.shared.b16 {%0,%1,%2,%3}, [%4];"
                 : "=r"(r0), "=r"(r1), "=r"(r2), "=r"(r3) : "r"(addr));
}
__device__ __forceinline__ void mma16816(float* d, const uint32_t* a, uint32_t b0, uint32_t b1) {
    asm volatile("mma.sync.aligned.m16n8k16.row.col.f32.f16.f16.f32 "
                 "{%0,%1,%2,%3}, {%4,%5,%6,%7}, {%8,%9}, {%0,%1,%2,%3};"
                 : "+f"(d[0]), "+f"(d[1]), "+f"(d[2]), "+f"(d[3])
                 : "r"(a[0]), "r"(a[1]), "r"(a[2]), "r"(a[3]), "r"(b0), "r"(b1));
}
__device__ __forceinline__ uint32_t packh2(float lo, float hi) {
    uint32_t r;
    asm("cvt.rn.f16x2.f32 %0, %1, %2;" : "=r"(r) : "f"(hi), "f"(lo));  // %1 -> high half
    return r;
}
__device__ __forceinline__ float sigm(float x) {
    return __fdividef(1.0f, 1.0f + __expf(-x));
}

// SMEM layout (bytes). Padded strides: U/V rows 144B, E rows 272B
// (16B shift per row mod 128B -> ldmatrix conflict-free without swizzle).
#define SM_U   0
#define SM_V0  18432                     // 2 stages x 128*144
#define SM_E0  (18432 * 3)               // 2 stages x 2*64*272 = 34816
#define VSTG   18432
#define ESTG   34816
#define SMEM_TOTAL (SM_E0 + 2 * ESTG)    // 124928

// ---------------------------------------------------------------------------
// Prep 1: V = U @ W (fp32 compute), write fp16 V and fp16 U row-major.
// ---------------------------------------------------------------------------
__global__ void __launch_bounds__(256) prep_kernel(
    const float* __restrict__ U, const float* __restrict__ W)
{
    __shared__ float sW[EDIM][EDIM + 1];
    __shared__ float sU[64][EDIM + 1];
    const int t = threadIdx.x, blk = blockIdx.x;
    for (int idx = t; idx < EDIM * EDIM; idx += 256)
        sW[idx / EDIM][idx % EDIM] = W[idx];
    for (int idx = t; idx < 64 * EDIM; idx += 256) {
        int r = idx / EDIM, e = idx % EDIM;
        sU[r][e] = U[(blk * 64 + r) * EDIM + e];
    }
    __syncthreads();
    const int i = t / 4, f0 = (t % 4) * 16;
    float acc[16];
#pragma unroll
    for (int k = 0; k < 16; k++) acc[k] = 0.f;
    for (int e = 0; e < EDIM; e++) {
        float u = sU[i][e];
#pragma unroll
        for (int k = 0; k < 16; k++) acc[k] = fmaf(u, sW[e][f0 + k], acc[k]);
    }
#pragma unroll
    for (int k = 0; k < 16; k++)
        g_Vh[(blk * 64 + i) * EDIM + f0 + k] = __float2half(acc[k]);
    for (int idx = t; idx < 64 * EDIM; idx += 256) {
        int r = idx / EDIM, e = idx % EDIM;
        g_Uh[(blk * 64 + r) * EDIM + e] = __float2half(sU[r][e]);
    }
}

// ---------------------------------------------------------------------------
// Prep 2: Et[b][d][i] = fp16( states[b][i][d] * relu(prof[b][i]-LEAK) )
// ---------------------------------------------------------------------------
__global__ void __launch_bounds__(256) gate_transpose_kernel(
    const float* __restrict__ states, const float* __restrict__ prof)
{
    __shared__ __half st[DDIM][136];
    const int t = threadIdx.x;
    const int bi = blockIdx.x;        // 64 blocks of 128 i
    const int b  = blockIdx.y;
    for (int idx = t; idx < 128 * 16; idx += 256) {
        int il = idx >> 4, d4 = idx & 15;
        int ig = bi * 128 + il;
        float g = prof[b * N_TASKS + ig] - LEAK;
        g = g > 0.f ? g : 0.f;
        float4 s4 = *(const float4*)&states[((size_t)b * N_TASKS + ig) * DDIM + d4 * 4];
        st[d4 * 4 + 0][il] = __float2half(s4.x * g);
        st[d4 * 4 + 1][il] = __float2half(s4.y * g);
        st[d4 * 4 + 2][il] = __float2half(s4.z * g);
        st[d4 * 4 + 3][il] = __float2half(s4.w * g);
    }
    __syncthreads();
    for (int idx = t; idx < 64 * 16; idx += 256) {
        int d = idx >> 4, ch = idx & 15;
        *(uint4*)&g_Et[((size_t)b * DDIM + d) * N_TASKS + bi * 128 + ch * 8] =
            *(const uint4*)&st[d][ch * 8];
    }
}

// ---------------------------------------------------------------------------
// Main kernel: mma.sync fp16 tensor cores, register-resident P repack.
// Grid: (64 j-tiles, 2 i-halves), 256 threads (8 warps, 16 j-rows each).
// ---------------------------------------------------------------------------
__global__ void __launch_bounds__(256, 1) mma_transfer_kernel(
    const float* __restrict__ bias_ptr)
{
    extern __shared__ char smem[];
    const uint32_t sb = smem_u32(smem);
    const int t = threadIdx.x, w = t >> 5, lane = t & 31;
    const int jt = blockIdx.x, half_id = blockIdx.y;
    const float bias = bias_ptr[0];
    const int lr = lane & 7, g = lane >> 3;
    const int qrow = lane >> 2, qcol = (lane & 3) * 2;

    // ---- issue tile-0 loads (cp.async), group 0 ----
    {
        const __half* vsrc = g_Vh + ((size_t)half_id * 4096) * 64;
        const uint32_t vdst = sb + SM_V0;
        for (int c = t; c < 1024; c += 256) {
            int r = c >> 3, ch = c & 7;
            cp16(vdst + r * 144 + ch * 16, vsrc + r * 64 + ch * 8);
        }
        const size_t ib = (size_t)half_id * 4096;
        const uint32_t edst = sb + SM_E0;
        for (int c = t; c < 2048; c += 256) {
            int b = c >> 10, rem = c & 1023;
            int d = rem >> 4, ch = rem & 15;
            cp16(edst + b * 17408 + d * 272 + ch * 16,
                 g_Et + ((size_t)(b * 64 + d)) * N_TASKS + ib + ch * 8);
        }
        cp_commit();
    }

    // ---- U tile -> SMEM (plain LDG/STS), then persistent A-fragments ----
    for (int c = t; c < 1024; c += 256) {
        int r = c >> 3, ch = c & 7;
        *(uint4*)(smem + SM_U + r * 144 + ch * 16) =
            *(const uint4*)(g_Uh + ((size_t)(jt * 128 + r)) * 64 + ch * 8);
    }
    __syncthreads();
    uint32_t uf[4][4];
#pragma unroll
    for (int kc = 0; kc < 4; kc++) {
        int row = w * 16 + (g & 1) * 8 + lr;
        int col = kc * 16 + (g >> 1) * 8;
        ldsm4(uf[kc][0], uf[kc][1], uf[kc][2], uf[kc][3],
              sb + SM_U + row * 144 + col * 2);
    }

    float accL[2][8][4];
#pragma unroll
    for (int b = 0; b < 2; b++)
#pragma unroll
        for (int nb = 0; nb < 8; nb++)
#pragma unroll
            for (int c = 0; c < 4; c++) accL[b][nb][c] = 0.f;

    const int diag_it = ((jt >> 5) == half_id) ? (jt & 31) : -1;
    const int jl0 = w * 16 + qrow;   // local j row of c0/c1 (c2/c3 -> +8)

    for (int it = 0; it < NT; it++) {
        __syncthreads();   // prior tile's SMEM reads done before overwrite
        if (it + 1 < NT) {
            const int nt = it + 1;
            const __half* vsrc = g_Vh + ((size_t)(half_id * 4096 + nt * 128)) * 64;
            const uint32_t vdst = sb + SM_V0 + (nt & 1) * VSTG;
            for (int c = t; c < 1024; c += 256) {
                int r = c >> 3, ch = c & 7;
                cp16(vdst + r * 144 + ch * 16, vsrc + r * 64 + ch * 8);
            }
            const size_t ib = (size_t)half_id * 4096 + (size_t)nt * 128;
            const uint32_t edst = sb + SM_E0 + (nt & 1) * ESTG;
            for (int c = t; c < 2048; c += 256) {
                int b = c >> 10, rem = c & 1023;
                int d = rem >> 4, ch = rem & 15;
                cp16(edst + b * 17408 + d * 272 + ch * 16,
                     g_Et + ((size_t)(b * 64 + d)) * N_TASKS + ib + ch * 8);
            }
            cp_commit();
            asm volatile("cp.async.wait_group 1;" ::: "memory");
        } else {
            asm volatile("cp.async.wait_group 0;" ::: "memory");
        }
        __syncthreads();

        const uint32_t vbase = sb + SM_V0 + (it & 1) * VSTG;
        const uint32_t ebase = sb + SM_E0 + (it & 1) * ESTG;

#pragma unroll
        for (int h = 0; h < 2; h++) {
            // ---- Phase A: S strip 16j x 64i ----
            float accS[8][4];
#pragma unroll
            for (int nb = 0; nb < 8; nb++)
#pragma unroll
                for (int c = 0; c < 4; c++) accS[nb][c] = 0.f;
#pragma unroll
            for (int kc = 0; kc < 4; kc++)
#pragma unroll
                for (int np = 0; np < 4; np++) {
                    uint32_t b0, b1, b2, b3;
                    int row = h * 64 + np * 16 + (g >> 1) * 8 + lr;
                    int col = kc * 16 + (g & 1) * 8;
                    ldsm4(b0, b1, b2, b3, vbase + row * 144 + col * 2);
                    mma16816(accS[np * 2],     uf[kc], b0, b1);
                    mma16816(accS[np * 2 + 1], uf[kc], b2, b3);
                }

            // ---- Epilogue: sigmoid + (rare) diag mask + repack to A-frags ----
            uint32_t pf[4][4];
#pragma unroll
            for (int nb = 0; nb < 8; nb++) {
                float p0 = sigm(accS[nb][0] + bias);
                float p1 = sigm(accS[nb][1] + bias);
                float p2 = sigm(accS[nb][2] + bias);
                float p3 = sigm(accS[nb][3] + bias);
                if (it == diag_it) {
                    int i0 = h * 64 + nb * 8 + qcol;
                    if (i0 == jl0)         p0 = 0.f;
                    if (i0 + 1 == jl0)     p1 = 0.f;
                    if (i0 == jl0 + 8)     p2 = 0.f;
                    if (i0 + 1 == jl0 + 8) p3 = 0.f;
                }
                pf[nb >> 1][(nb & 1) * 2 + 0] = packh2(p0, p1);
                pf[nb >> 1][(nb & 1) * 2 + 1] = packh2(p2, p3);
            }

            // ---- Phase B: leaked += P . E_b ----
#pragma unroll
            for (int kbl = 0; kbl < 4; kbl++) {
                int colb = (h * 4 + kbl) * 16 + (g & 1) * 8;
#pragma unroll
                for (int b = 0; b < 2; b++)
#pragma unroll
                    for (int p = 0; p < 4; p++) {
                        int rowd = p * 16 + (g >> 1) * 8 + lr;
                        uint32_t e0, e1, e2, e3;
                        ldsm4(e0, e1, e2, e3,
                              ebase + b * 17408 + rowd * 272 + colb * 2);
                        mma16816(accL[b][p * 2],     pf[kbl], e0, e1);
                        mma16816(accL[b][p * 2 + 1], pf[kbl], e2, e3);
                    }
            }
        }
    }

    // ---- store partial leaked ----
    const int j0 = jt * 128 + w * 16 + qrow;
#pragma unroll
    for (int b = 0; b < 2; b++)
#pragma unroll
        for (int nb = 0; nb < 8; nb++) {
            float* dst = g_part + (((size_t)(half_id * 2 + b)) * N_TASKS + j0) * DDIM
                         + nb * 8 + qcol;
            float2 v0 = make_float2(accL[b][nb][0], accL[b][nb][1]);
            float2 v1 = make_float2(accL[b][nb][2], accL[b][nb][3]);
            *(float2*)dst = v0;
            *(float2*)(dst + 8 * DDIM) = v1;
        }
}

// ---------------------------------------------------------------------------
// Reduce: out = states + part[half0] + part[half1]
// ---------------------------------------------------------------------------
__global__ void __launch_bounds__(256) reduce_kernel(
    const float* __restrict__ states, float* __restrict__ out)
{
    const size_t f4 = (size_t)blockIdx.x * 256 + threadIdx.x;
    const size_t total4 = (size_t)BB * N_TASKS * DDIM / 4;
    if (f4 >= total4) return;
    const float4 s  = ((const float4*)states)[f4];
    const float4 p0 = ((const float4*)g_part)[f4];
    const float4 p1 = ((const float4*)g_part)[total4 + f4];
    float4 o;
    o.x = s.x + p0.x + p1.x;
    o.y = s.y + p0.y + p1.y;
    o.z = s.z + p0.z + p1.z;
    o.w = s.w + p0.w + p1.w;
    ((float4*)out)[f4] = o;
}

// ---------------------------------------------------------------------------
extern "C" void kernel_launch(void* const* d_in, const int* in_sizes, int n_in,
                              void* d_out, int out_size)
{
    const float* states = (const float*)d_in[0];   // [2, 8192, 64]
    const float* prof   = (const float*)d_in[1];   // [2, 8192]
    const float* U      = (const float*)d_in[2];   // [8192, 64]
    const float* W      = (const float*)d_in[3];   // [1, 64, 64]
    const float* bias   = (const float*)d_in[4];   // [1]
    float* out          = (float*)d_out;           // [2, 8192, 64]

    cudaFuncSetAttribute(mma_transfer_kernel,
                         cudaFuncAttributeMaxDynamicSharedMemorySize, SMEM_TOTAL);

    prep_kernel<<<N_TASKS / 64, 256>>>(U, W);
    gate_transpose_kernel<<<dim3(N_TASKS / 128, BB), 256>>>(states, prof);
    mma_transfer_kernel<<<dim3(N_TASKS / 128, 2), 256, SMEM_TOTAL>>>(bias);
    const int total4 = BB * N_TASKS * DDIM / 4;
    reduce_kernel<<<(total4 + 255) / 256, 256>>>(states, out);
}

// round 11
// speedup vs baseline: 12.6524x; 1.0501x over previous
#include <cuda_runtime.h>
#include <cuda_fp16.h>
#include <cstdint>
#include <math.h>

#define N_TASKS 8192
#define EDIM 64
#define DDIM 64
#define BB 2
#define NT 32           // i-tiles per CTA (half of N / 128)
#define LEAK 0.7f

// ---------------- device scratch (no runtime allocation) -------------------
__device__ __half g_Uh[N_TASKS * EDIM];            // fp16 U  [i][e]
__device__ __half g_Vh[N_TASKS * EDIM];            // fp16 V=U@W  [i][e]
__device__ __half g_Et[BB * DDIM * N_TASKS];       // fp16 gated states^T [b][d][i]

// ---------------- PTX helpers ----------------------------------------------
__device__ __forceinline__ uint32_t smem_u32(const void* p) {
    uint32_t a;
    asm("{ .reg .u64 t; cvta.to.shared.u64 t, %1; cvt.u32.u64 %0, t; }" : "=r"(a) : "l"(p));
    return a;
}
__device__ __forceinline__ void cp16(uint32_t dst, const void* src) {
    asm volatile("cp.async.ca.shared.global [%0], [%1], 16;" :: "r"(dst), "l"(src) : "memory");
}
__device__ __forceinline__ void cp_commit() {
    asm volatile("cp.async.commit_group;" ::: "memory");
}
__device__ __forceinline__ void ldsm4(uint32_t& r0, uint32_t& r1, uint32_t& r2, uint32_t& r3,
                                      uint32_t addr) {
    asm volatile("ldmatrix.sync.aligned.m8n8.x4.shared.b16 {%0,%1,%2,%3}, [%4];"
                 : "=r"(r0), "=r"(r1), "=r"(r2), "=r"(r3) : "r"(addr));
}
__device__ __forceinline__ void mma16816(float* d, const uint32_t* a, uint32_t b0, uint32_t b1) {
    asm volatile("mma.sync.aligned.m16n8k16.row.col.f32.f16.f16.f32 "
                 "{%0,%1,%2,%3}, {%4,%5,%6,%7}, {%8,%9}, {%0,%1,%2,%3};"
                 : "+f"(d[0]), "+f"(d[1]), "+f"(d[2]), "+f"(d[3])
                 : "r"(a[0]), "r"(a[1]), "r"(a[2]), "r"(a[3]), "r"(b0), "r"(b1));
}
__device__ __forceinline__ uint32_t packh2(float lo, float hi) {
    uint32_t r;
    asm("cvt.rn.f16x2.f32 %0, %1, %2;" : "=r"(r) : "f"(hi), "f"(lo));  // %2 -> low half
    return r;
}
// sigmoid(x + b) = 0.5*tanh(0.5*x + 0.5*b) + 0.5   (1 MUFU, no div)
__device__ __forceinline__ float sigm_t(float x, float bh) {
    float y;
    asm("tanh.approx.f32 %0, %1;" : "=f"(y) : "f"(fmaf(x, 0.5f, bh)));
    return fmaf(y, 0.5f, 0.5f);
}
__device__ __forceinline__ void red2(float* dst, float a, float b) {
    asm volatile("red.global.add.v2.f32 [%0], {%1, %2};" :: "l"(dst), "f"(a), "f"(b) : "memory");
}

// SMEM layout (bytes). Padded strides: U/V rows 144B, E rows 272B
#define SM_U   0
#define SM_V0  18432                     // 2 stages x 128*144
#define SM_E0  (18432 * 3)               // 2 stages x 2*64*272 = 34816
#define VSTG   18432
#define ESTG   34816
#define SMEM_TOTAL (SM_E0 + 2 * ESTG)    // 124928

// ---------------------------------------------------------------------------
// Fused prep: blocks [0,128): V = U@W + fp16 casts.  blocks [128,256):
// Et[b][d][i] = fp16(states[b][i][d] * relu(prof[b][i]-LEAK)).
// ---------------------------------------------------------------------------
__global__ void __launch_bounds__(256) prep_all_kernel(
    const float* __restrict__ U, const float* __restrict__ W,
    const float* __restrict__ states, const float* __restrict__ prof)
{
    __shared__ float sW[EDIM][EDIM + 1];
    __shared__ float sU[64][EDIM + 1];
    __shared__ __half st[DDIM][136];
    const int t = threadIdx.x;

    if (blockIdx.x < 128) {
        const int blk = blockIdx.x;
        for (int idx = t; idx < EDIM * EDIM; idx += 256)
            sW[idx / EDIM][idx % EDIM] = W[idx];
        for (int idx = t; idx < 64 * EDIM; idx += 256) {
            int r = idx / EDIM, e = idx % EDIM;
            sU[r][e] = U[(blk * 64 + r) * EDIM + e];
        }
        __syncthreads();
        const int i = t / 4, f0 = (t % 4) * 16;
        float acc[16];
#pragma unroll
        for (int k = 0; k < 16; k++) acc[k] = 0.f;
        for (int e = 0; e < EDIM; e++) {
            float u = sU[i][e];
#pragma unroll
            for (int k = 0; k < 16; k++) acc[k] = fmaf(u, sW[e][f0 + k], acc[k]);
        }
#pragma unroll
        for (int k = 0; k < 16; k++)
            g_Vh[(blk * 64 + i) * EDIM + f0 + k] = __float2half(acc[k]);
        for (int idx = t; idx < 64 * EDIM; idx += 256) {
            int r = idx / EDIM, e = idx % EDIM;
            g_Uh[(blk * 64 + r) * EDIM + e] = __float2half(sU[r][e]);
        }
    } else {
        const int bi = (blockIdx.x - 128) & 63;
        const int b  = (blockIdx.x - 128) >> 6;
        for (int idx = t; idx < 128 * 16; idx += 256) {
            int il = idx >> 4, d4 = idx & 15;
            int ig = bi * 128 + il;
            float g = prof[b * N_TASKS + ig] - LEAK;
            g = g > 0.f ? g : 0.f;
            float4 s4 = *(const float4*)&states[((size_t)b * N_TASKS + ig) * DDIM + d4 * 4];
            st[d4 * 4 + 0][il] = __float2half(s4.x * g);
            st[d4 * 4 + 1][il] = __float2half(s4.y * g);
            st[d4 * 4 + 2][il] = __float2half(s4.z * g);
            st[d4 * 4 + 3][il] = __float2half(s4.w * g);
        }
        __syncthreads();
        for (int idx = t; idx < 64 * 16; idx += 256) {
            int d = idx >> 4, ch = idx & 15;
            *(uint4*)&g_Et[((size_t)b * DDIM + d) * N_TASKS + bi * 128 + ch * 8] =
                *(const uint4*)&st[d][ch * 8];
        }
    }
}

// ---------------------------------------------------------------------------
// Main kernel: mma.sync fp16 tensor cores; P repacked in registers;
// result accumulated straight into out via red.global (out pre-set = states).
// Grid: (64 j-tiles, 2 i-halves), 256 threads (8 warps).
// ---------------------------------------------------------------------------
__global__ void __launch_bounds__(256, 1) mma_transfer_kernel(
    const float* __restrict__ bias_ptr, float* __restrict__ out)
{
    extern __shared__ char smem[];
    const uint32_t sb = smem_u32(smem);
    const int t = threadIdx.x, w = t >> 5, lane = t & 31;
    const int jt = blockIdx.x, half_id = blockIdx.y;
    const float bh = 0.5f * bias_ptr[0];
    const int lr = lane & 7, g = lane >> 3;
    const int qrow = lane >> 2, qcol = (lane & 3) * 2;

    // ---- issue tile-0 loads (cp.async) ----
    {
        const __half* vsrc = g_Vh + ((size_t)half_id * 4096) * 64;
        const uint32_t vdst = sb + SM_V0;
        for (int c = t; c < 1024; c += 256) {
            int r = c >> 3, ch = c & 7;
            cp16(vdst + r * 144 + ch * 16, vsrc + r * 64 + ch * 8);
        }
        const size_t ib = (size_t)half_id * 4096;
        const uint32_t edst = sb + SM_E0;
        for (int c = t; c < 2048; c += 256) {
            int b = c >> 10, rem = c & 1023;
            int d = rem >> 4, ch = rem & 15;
            cp16(edst + b * 17408 + d * 272 + ch * 16,
                 g_Et + ((size_t)(b * 64 + d)) * N_TASKS + ib + ch * 8);
        }
        cp_commit();
    }

    // ---- U tile -> SMEM, then persistent A-fragments ----
    for (int c = t; c < 1024; c += 256) {
        int r = c >> 3, ch = c & 7;
        *(uint4*)(smem + SM_U + r * 144 + ch * 16) =
            *(const uint4*)(g_Uh + ((size_t)(jt * 128 + r)) * 64 + ch * 8);
    }
    __syncthreads();
    uint32_t uf[4][4];
#pragma unroll
    for (int kc = 0; kc < 4; kc++) {
        int row = w * 16 + (g & 1) * 8 + lr;
        int col = kc * 16 + (g >> 1) * 8;
        ldsm4(uf[kc][0], uf[kc][1], uf[kc][2], uf[kc][3],
              sb + SM_U + row * 144 + col * 2);
    }

    float accL[2][8][4];
#pragma unroll
    for (int b = 0; b < 2; b++)
#pragma unroll
        for (int nb = 0; nb < 8; nb++)
#pragma unroll
            for (int c = 0; c < 4; c++) accL[b][nb][c] = 0.f;

    const int diag_it = ((jt >> 5) == half_id) ? (jt & 31) : -1;
    const int jl0 = w * 16 + qrow;

    for (int it = 0; it < NT; it++) {
        __syncthreads();
        if (it + 1 < NT) {
            const int nt = it + 1;
            const __half* vsrc = g_Vh + ((size_t)(half_id * 4096 + nt * 128)) * 64;
            const uint32_t vdst = sb + SM_V0 + (nt & 1) * VSTG;
            for (int c = t; c < 1024; c += 256) {
                int r = c >> 3, ch = c & 7;
                cp16(vdst + r * 144 + ch * 16, vsrc + r * 64 + ch * 8);
            }
            const size_t ib = (size_t)half_id * 4096 + (size_t)nt * 128;
            const uint32_t edst = sb + SM_E0 + (nt & 1) * ESTG;
            for (int c = t; c < 2048; c += 256) {
                int b = c >> 10, rem = c & 1023;
                int d = rem >> 4, ch = rem & 15;
                cp16(edst + b * 17408 + d * 272 + ch * 16,
                     g_Et + ((size_t)(b * 64 + d)) * N_TASKS + ib + ch * 8);
            }
            cp_commit();
            asm volatile("cp.async.wait_group 1;" ::: "memory");
        } else {
            asm volatile("cp.async.wait_group 0;" ::: "memory");
        }
        __syncthreads();

        const uint32_t vbase = sb + SM_V0 + (it & 1) * VSTG;
        const uint32_t ebase = sb + SM_E0 + (it & 1) * ESTG;

#pragma unroll
        for (int h = 0; h < 2; h++) {
            // ---- Phase A: S strip 16j x 64i ----
            float accS[8][4];
#pragma unroll
            for (int nb = 0; nb < 8; nb++)
#pragma unroll
                for (int c = 0; c < 4; c++) accS[nb][c] = 0.f;
#pragma unroll
            for (int kc = 0; kc < 4; kc++)
#pragma unroll
                for (int np = 0; np < 4; np++) {
                    uint32_t b0, b1, b2, b3;
                    int row = h * 64 + np * 16 + (g >> 1) * 8 + lr;
                    int col = kc * 16 + (g & 1) * 8;
                    ldsm4(b0, b1, b2, b3, vbase + row * 144 + col * 2);
                    mma16816(accS[np * 2],     uf[kc], b0, b1);
                    mma16816(accS[np * 2 + 1], uf[kc], b2, b3);
                }

            // ---- Epilogue: tanh-sigmoid + rare diag mask + repack ----
            uint32_t pf[4][4];
#pragma unroll
            for (int nb = 0; nb < 8; nb++) {
                float p0 = sigm_t(accS[nb][0], bh);
                float p1 = sigm_t(accS[nb][1], bh);
                float p2 = sigm_t(accS[nb][2], bh);
                float p3 = sigm_t(accS[nb][3], bh);
                if (it == diag_it) {
                    int i0 = h * 64 + nb * 8 + qcol;
                    if (i0 == jl0)         p0 = 0.f;
                    if (i0 + 1 == jl0)     p1 = 0.f;
                    if (i0 == jl0 + 8)     p2 = 0.f;
                    if (i0 + 1 == jl0 + 8) p3 = 0.f;
                }
                pf[nb >> 1][(nb & 1) * 2 + 0] = packh2(p0, p1);
                pf[nb >> 1][(nb & 1) * 2 + 1] = packh2(p2, p3);
            }

            // ---- Phase B: leaked += P . E_b ----
#pragma unroll
            for (int kbl = 0; kbl < 4; kbl++) {
                int colb = (h * 4 + kbl) * 16 + (g & 1) * 8;
#pragma unroll
                for (int b = 0; b < 2; b++)
#pragma unroll
                    for (int p = 0; p < 4; p++) {
                        int rowd = p * 16 + (g >> 1) * 8 + lr;
                        uint32_t e0, e1, e2, e3;
                        ldsm4(e0, e1, e2, e3,
                              ebase + b * 17408 + rowd * 272 + colb * 2);
                        mma16816(accL[b][p * 2],     pf[kbl], e0, e1);
                        mma16816(accL[b][p * 2 + 1], pf[kbl], e2, e3);
                    }
            }
        }
    }

    // ---- accumulate into out (pre-initialized to states via memcpy) ----
    const int j0 = jt * 128 + w * 16 + qrow;
#pragma unroll
    for (int b = 0; b < 2; b++)
#pragma unroll
        for (int nb = 0; nb < 8; nb++) {
            float* dst = out + ((size_t)b * N_TASKS + j0) * DDIM + nb * 8 + qcol;
            red2(dst,            accL[b][nb][0], accL[b][nb][1]);
            red2(dst + 8 * DDIM, accL[b][nb][2], accL[b][nb][3]);
        }
}

// ---------------------------------------------------------------------------
extern "C" void kernel_launch(void* const* d_in, const int* in_sizes, int n_in,
                              void* d_out, int out_size)
{
    const float* states = (const float*)d_in[0];   // [2, 8192, 64]
    const float* prof   = (const float*)d_in[1];   // [2, 8192]
    const float* U      = (const float*)d_in[2];   // [8192, 64]
    const float* W      = (const float*)d_in[3];   // [1, 64, 64]
    const float* bias   = (const float*)d_in[4];   // [1]
    float* out          = (float*)d_out;           // [2, 8192, 64]

    cudaFuncSetAttribute(mma_transfer_kernel,
                         cudaFuncAttributeMaxDynamicSharedMemorySize, SMEM_TOTAL);

    // out = states (graph-capturable async D2D), then kernels RED-add leaked.
    cudaMemcpyAsync(out, states, (size_t)BB * N_TASKS * DDIM * sizeof(float),
                    cudaMemcpyDeviceToDevice, 0);
    prep_all_kernel<<<256, 256>>>(U, W, states, prof);
    mma_transfer_kernel<<<dim3(N_TASKS / 128, 2), 256, SMEM_TOTAL>>>(bias, out);
}